// round 10
// baseline (speedup 1.0000x reference)
#include <cuda_runtime.h>
#include <cuda_bf16.h>
#include <cooperative_groups.h>

namespace cg = cooperative_groups;

#define D    256
#define F    1024
#define NL   4
#define NC   10
#define TPB  256
#define M    4      // batch elements per cluster

__device__ __forceinline__ float gelu_tanh(float x) {
    const float c = 0.7978845608028654f;
    float u = c * (x + 0.044715f * x * x * x);
    return 0.5f * x * (1.0f + tanhf(u));
}

template<int CSZ>
__global__ void __launch_bounds__(TPB, 1)
performer_cls_kernel(const int*   __restrict__ xx,
                     const float* __restrict__ emb_tok,
                     const float* __restrict__ emb_pos,
                     const float* __restrict__ ln1_s,
                     const float* __restrict__ ln1_b,
                     const float* __restrict__ wv,
                     const float* __restrict__ wo,
                     const float* __restrict__ bo,
                     const float* __restrict__ ln2_s,
                     const float* __restrict__ ln2_b,
                     const float* __restrict__ w1,
                     const float* __restrict__ b1v,
                     const float* __restrict__ w2,
                     const float* __restrict__ b2v,
                     const float* __restrict__ wcls,
                     const float* __restrict__ bcls,
                     float* __restrict__ out,
                     int N)
{
    // ---- derived geometry ----
    constexpr int CHA = D / CSZ;          // A/C col-chunk (32 / 16)
    constexpr int GA  = CHA / 4;          // float4 groups (8 / 4)
    constexpr int SA  = TPB / GA;         // K-slices (32 / 64)
    constexpr int RA  = D / SA;           // rows/slice, K=D (8 / 4)
    constexpr int RC  = F / SA;           // rows/slice, K=F (32 / 16)
    constexpr int CHB = F / CSZ;          // B col-chunk (128 / 64)
    constexpr int GB  = CHB / 4;          // (32 / 16)
    constexpr int SB  = TPB / GB;         // (8 / 16)
    constexpr int RB  = D / SB;           // (32 / 16)
    constexpr int STA = M * GA + 1;       // A/C partial stride (f4)
    constexpr int STB = M * GB + 1;       // B partial stride (f4)
    constexpr int PS4N = (SA * STA > SB * STB ? SA * STA : SB * STB);
    constexpr int LPR = TPB / CSZ;        // lanes per rank-group

    __shared__ float  sh_y[M * D];
    __shared__ float  sh_v[M * D];
    __shared__ float  sh_g[M * F];
    __shared__ float  sh_o[M * D];
    __shared__ float  sh_c[M * CHB];
    __shared__ float4 ps4[PS4N];
    __shared__ float  red[80];

    float* psf = (float*)ps4;

    cg::cluster_group cluster = cg::this_cluster();
    const int tid = threadIdx.x;
    const int r   = (int)cluster.block_rank();
    const int b0  = (blockIdx.x / CSZ) * M;

    const int c4  = tid & (GA - 1);
    const int ks  = tid / GA;
    const int c4b = tid & (GB - 1);
    const int ksb = tid / GB;
    const int j0  = r * CHA;
    const int j0b = r * CHB;
    const int rk   = tid / LPR;
    const int lane = tid % LPR;

    // ---------- LN (M batches) ----------
    auto layer_norm = [&](const float* hv, const float* sc, const float* bi) {
        float s[M], q[M];
        #pragma unroll
        for (int m = 0; m < M; ++m) { s[m] = hv[m]; q[m] = hv[m] * hv[m]; }
        #pragma unroll
        for (int o = 16; o > 0; o >>= 1) {
            #pragma unroll
            for (int m = 0; m < M; ++m) {
                s[m] += __shfl_xor_sync(0xffffffffu, s[m], o);
                q[m] += __shfl_xor_sync(0xffffffffu, q[m], o);
            }
        }
        int wid = tid >> 5;
        if ((tid & 31) == 0) {
            #pragma unroll
            for (int m = 0; m < M; ++m) {
                red[wid * 8 + m]     = s[m];
                red[wid * 8 + 4 + m] = q[m];
            }
        }
        __syncthreads();
        if (tid < 8) {
            float acc = 0.0f;
            #pragma unroll
            for (int w = 0; w < 8; ++w) acc += red[w * 8 + tid];
            red[64 + tid] = acc;
        }
        __syncthreads();
        #pragma unroll
        for (int m = 0; m < M; ++m) {
            float mu  = red[64 + m] * (1.0f / D);
            float var = red[64 + 4 + m] * (1.0f / D) - mu * mu;
            float inv = rsqrtf(var + 1e-5f);
            sh_y[m * D + tid] = (hv[m] - mu) * inv * sc[tid] + bi[tid];
        }
        __syncthreads();
    };

    // ---------- D-K chunk matvec (A stages) ----------
    auto matvecA = [&](const float* in, const float4* W4) {
        float4 a[M];
        #pragma unroll
        for (int m = 0; m < M; ++m) a[m] = make_float4(0.f, 0.f, 0.f, 0.f);
        #pragma unroll
        for (int i = 0; i < RA; ++i) {
            int k = ks * RA + i;
            float4 w = W4[k * (D / 4) + r * GA + c4];
            #pragma unroll
            for (int m = 0; m < M; ++m) {
                float yk = in[m * D + k];
                a[m].x = fmaf(yk, w.x, a[m].x); a[m].y = fmaf(yk, w.y, a[m].y);
                a[m].z = fmaf(yk, w.z, a[m].z); a[m].w = fmaf(yk, w.w, a[m].w);
            }
        }
        #pragma unroll
        for (int m = 0; m < M; ++m) ps4[ks * STA + m * GA + c4] = a[m];
        __syncthreads();
        if (tid < M * CHA) {
            int m = tid / CHA, col = tid % CHA;
            float acc = 0.0f;
            #pragma unroll
            for (int s = 0; s < SA; ++s) acc += psf[s * STA * 4 + m * CHA + col];
            sh_c[m * CHA + col] = acc;
        }
        __syncthreads();
    };

    auto bcastA = [&](float* sym) {
        float* dst = cluster.map_shared_rank(sym, rk);
        #pragma unroll
        for (int jj = 0; jj < M * CHA / LPR; ++jj) {
            int idx = jj * LPR + lane;
            int m = idx / CHA, col = idx % CHA;
            dst[m * D + j0 + col] = sh_c[idx];
        }
    };

    // ---- init ----
    float hv[M];
    #pragma unroll
    for (int m = 0; m < M; ++m) {
        const int tok = xx[(size_t)(b0 + m) * N];
        hv[m] = emb_tok[(size_t)tok * D + tid] + emb_pos[tid];
    }

    for (int l = 0; l < NL; ++l) {
        // ======== A1: v0 = LN1(h) @ wv ========
        layer_norm(hv, ln1_s + l * D, ln1_b + l * D);
        matvecA(sh_y, (const float4*)(wv + (size_t)l * D * D));
        bcastA(sh_v);
        cluster.sync();

        // ======== A2: o = v0 @ wo ========
        matvecA(sh_v, (const float4*)(wo + (size_t)l * D * D));
        bcastA(sh_o);
        cluster.sync();
        #pragma unroll
        for (int m = 0; m < M; ++m)
            hv[m] += sh_o[m * D + tid] + bo[l * D + tid];

        // ======== B: hidden = gelu(LN2(h) @ w1 + b1) ========
        layer_norm(hv, ln2_s + l * D, ln2_b + l * D);
        {
            const float4* W14 = (const float4*)(w1 + (size_t)l * D * F);
            float4 a[M];
            #pragma unroll
            for (int m = 0; m < M; ++m) a[m] = make_float4(0.f, 0.f, 0.f, 0.f);
            #pragma unroll
            for (int i = 0; i < RB; ++i) {
                int k = ksb * RB + i;
                float4 w = W14[k * (F / 4) + r * GB + c4b];
                #pragma unroll
                for (int m = 0; m < M; ++m) {
                    float yk = sh_y[m * D + k];
                    a[m].x = fmaf(yk, w.x, a[m].x); a[m].y = fmaf(yk, w.y, a[m].y);
                    a[m].z = fmaf(yk, w.z, a[m].z); a[m].w = fmaf(yk, w.w, a[m].w);
                }
            }
            #pragma unroll
            for (int m = 0; m < M; ++m) ps4[ksb * STB + m * GB + c4b] = a[m];
            __syncthreads();
            #pragma unroll
            for (int t = 0; t < (M * CHB + TPB - 1) / TPB; ++t) {
                int o = tid + t * TPB;
                if (o < M * CHB) {
                    int m = o / CHB, col = o % CHB;
                    float acc = b1v[l * F + j0b + col];
                    #pragma unroll
                    for (int s = 0; s < SB; ++s)
                        acc += psf[s * STB * 4 + m * CHB + col];
                    sh_c[m * CHB + col] = gelu_tanh(acc);
                }
            }
            __syncthreads();
            float* dst = cluster.map_shared_rank(sh_g, rk);
            #pragma unroll
            for (int jj = 0; jj < M * CHB / LPR; ++jj) {
                int idx = jj * LPR + lane;
                int m = idx / CHB, col = idx % CHB;
                dst[m * F + j0b + col] = sh_c[idx];
            }
        }
        cluster.sync();

        // ======== C: delta = hidden @ w2 ========
        {
            const float4* W24 = (const float4*)(w2 + (size_t)l * F * D);
            float4 a[M];
            #pragma unroll
            for (int m = 0; m < M; ++m) a[m] = make_float4(0.f, 0.f, 0.f, 0.f);
            #pragma unroll
            for (int i = 0; i < RC; ++i) {
                int k = ks * RC + i;
                float4 w = W24[k * (D / 4) + r * GA + c4];
                #pragma unroll
                for (int m = 0; m < M; ++m) {
                    float yk = sh_g[m * F + k];
                    a[m].x = fmaf(yk, w.x, a[m].x); a[m].y = fmaf(yk, w.y, a[m].y);
                    a[m].z = fmaf(yk, w.z, a[m].z); a[m].w = fmaf(yk, w.w, a[m].w);
                }
            }
            #pragma unroll
            for (int m = 0; m < M; ++m) ps4[ks * STA + m * GA + c4] = a[m];
            __syncthreads();
            if (tid < M * CHA) {
                int m = tid / CHA, col = tid % CHA;
                float acc = 0.0f;
                #pragma unroll
                for (int s = 0; s < SA; ++s)
                    acc += psf[s * STA * 4 + m * CHA + col];
                sh_c[m * CHA + col] = acc;
            }
            __syncthreads();
            bcastA(sh_o);
        }
        cluster.sync();
        #pragma unroll
        for (int m = 0; m < M; ++m)
            hv[m] += sh_o[m * D + tid] + b2v[l * D + tid];
    }

    // ======== classifier (rank 0) ========
    if (r == 0) {
        #pragma unroll
        for (int m = 0; m < M; ++m) sh_y[m * D + tid] = hv[m];
        __syncthreads();
        if (tid < 160) {
            const int c = tid >> 4;
            const int s = tid & 15;
            #pragma unroll
            for (int m = 0; m < M; ++m) {
                float acc = 0.0f;
                #pragma unroll
                for (int i = 0; i < 16; ++i) {
                    int k = s * 16 + i;
                    acc = fmaf(sh_y[m * D + k], wcls[k * NC + c], acc);
                }
                psf[m * 176 + c * 17 + s] = acc;
            }
        }
        __syncthreads();
        if (tid < NC) {
            #pragma unroll
            for (int m = 0; m < M; ++m) {
                float acc = bcls[tid];
                #pragma unroll
                for (int s = 0; s < 16; ++s) acc += psf[m * 176 + tid * 17 + s];
                out[(size_t)(b0 + m) * NC + tid] = acc;
            }
        }
    }
}

extern "C" void kernel_launch(void* const* d_in, const int* in_sizes, int n_in,
                              void* d_out, int out_size)
{
    const int*   xx      = (const int*)  d_in[0];
    const float* emb_tok = (const float*)d_in[1];
    const float* emb_pos = (const float*)d_in[2];
    const float* ln1_s   = (const float*)d_in[4];
    const float* ln1_b   = (const float*)d_in[5];
    const float* wv      = (const float*)d_in[8];
    const float* wo      = (const float*)d_in[9];
    const float* bo      = (const float*)d_in[10];
    const float* ln2_s   = (const float*)d_in[11];
    const float* ln2_b   = (const float*)d_in[12];
    const float* w1      = (const float*)d_in[13];
    const float* b1v     = (const float*)d_in[14];
    const float* w2      = (const float*)d_in[15];
    const float* b2v     = (const float*)d_in[16];
    const float* wcls    = (const float*)d_in[17];
    const float* bcls    = (const float*)d_in[18];
    float* out = (float*)d_out;

    const int B = out_size / NC;          // 16
    const int N = in_sizes[0] / B;        // 4096

    // try CS=16 (nonportable); fall back to the proven CS=8 config
    cudaError_t e = cudaFuncSetAttribute(
        (const void*)performer_cls_kernel<16>,
        cudaFuncAttributeNonPortableClusterSizeAllowed, 1);
    (void)cudaGetLastError();   // clear any sticky error from a failed attr set
    const int csz = (e == cudaSuccess) ? 16 : 8;

    cudaLaunchConfig_t cfg = {};
    cfg.blockDim = {TPB, 1, 1};
    cfg.gridDim  = {(unsigned)((B / M) * csz), 1, 1};
    cfg.dynamicSmemBytes = 0;
    cudaLaunchAttribute attrs[1];
    attrs[0].id = cudaLaunchAttributeClusterDimension;
    attrs[0].val.clusterDim = {(unsigned)csz, 1, 1};
    cfg.attrs = attrs;
    cfg.numAttrs = 1;

    if (csz == 16) {
        cudaLaunchKernelEx(&cfg, performer_cls_kernel<16>,
                           xx, emb_tok, emb_pos, ln1_s, ln1_b, wv, wo, bo,
                           ln2_s, ln2_b, w1, b1v, w2, b2v, wcls, bcls, out, N);
    } else {
        cudaLaunchKernelEx(&cfg, performer_cls_kernel<8>,
                           xx, emb_tok, emb_pos, ln1_s, ln1_b, wv, wo, bo,
                           ln2_s, ln2_b, w1, b1v, w2, b2v, wcls, bcls, out, N);
    }
}